// round 13
// baseline (speedup 1.0000x reference)
#include <cuda_runtime.h>
#include <cuda_bf16.h>

#define N_NODES 100000
#define E_EDGES 1250000
#define DIM     64
#define NL      3
#define SCAN_B  256
#define SCAN_NBLK ((N_NODES + SCAN_B - 1) / SCAN_B)   // 391

// ---- scratch (no allocations allowed) ----
__device__ float g_w[NL + 1];
__device__ int   g_cnt[N_NODES];
__device__ int   g_rank[E_EDGES];
__device__ int   g_excl[N_NODES];
__device__ int   g_bsum[512];
__device__ int   g_boff[512];
__device__ int   g_csrc[E_EDGES];
__device__ float g_cw[E_EDGES];
__device__ float g_dis[N_NODES];
__device__ float g_x1[N_NODES * DIM];
__device__ float g_x2[N_NODES * DIM];
__device__ float g_out[N_NODES * DIM];

// histogram; atomic return value = unique within-row rank
__global__ void k_count(const int* __restrict__ edge_index) {
    int e = blockIdx.x * blockDim.x + threadIdx.x;
    if (e < E_EDGES)
        g_rank[e] = atomicAdd(&g_cnt[edge_index[E_EDGES + e]], 1);
}

// per-block scan + block sums; also dis = rsqrt(deg) (fused)
__global__ void k_scan1() {
    __shared__ int sh[SCAN_B];
    int t = threadIdx.x, b = blockIdx.x, i = b * SCAN_B + t;
    int v = (i < N_NODES) ? g_cnt[i] : 0;
    if (i < N_NODES)
        g_dis[i] = (v > 0) ? rsqrtf((float)v) : 0.f;
    sh[t] = v; __syncthreads();
    #pragma unroll
    for (int off = 1; off < SCAN_B; off <<= 1) {
        int u = (t >= off) ? sh[t - off] : 0;
        __syncthreads();
        sh[t] += u;
        __syncthreads();
    }
    if (i < N_NODES) g_excl[i] = sh[t] - v;
    if (t == SCAN_B - 1) g_bsum[b] = sh[t];
}

// scan the 391 block sums in a single 512-thread block; thread 0 also does softmax
__global__ void k_scan2(const float* __restrict__ alpha) {
    __shared__ int sh[512];
    int t = threadIdx.x;
    if (t == 0) {
        float m = alpha[0];
        for (int j = 1; j <= NL; j++) m = fmaxf(m, alpha[j]);
        float s = 0.f, e[NL + 1];
        for (int j = 0; j <= NL; j++) { e[j] = __expf(alpha[j] - m); s += e[j]; }
        for (int j = 0; j <= NL; j++) g_w[j] = e[j] / s;
    }
    int v = (t < SCAN_NBLK) ? g_bsum[t] : 0;
    sh[t] = v; __syncthreads();
    #pragma unroll
    for (int off = 1; off < 512; off <<= 1) {
        int u = (t >= off) ? sh[t - off] : 0;
        __syncthreads();
        sh[t] += u;
        __syncthreads();
    }
    if (t < SCAN_NBLK) g_boff[t] = sh[t] - v;
}

// rowptr(i) computed on the fly by consumers: g_excl[i] + g_boff[i >> 8]
__device__ __forceinline__ int rowptr_at(int i) {
    return (i < N_NODES) ? (g_excl[i] + g_boff[i >> 8]) : E_EDGES;
}

// fill CSR: no atomics (rank precomputed); payload = src index + dis[src].
// dis[dst] factor applied in gather epilogue (row-uniform).
__global__ void k_fill(const int* __restrict__ edge_index) {
    int e = blockIdx.x * blockDim.x + threadIdx.x;
    if (e < E_EDGES) {
        int s = edge_index[e];
        int t = edge_index[E_EDGES + e];
        int pos = g_excl[t] + __ldg(&g_boff[t >> 8]) + g_rank[e];
        g_csrc[pos] = s;
        g_cw[pos]   = g_dis[s];
    }
}

// Gather propagation: one warp per dst node, float2 per lane (256B row).
// Edge metadata loaded 4-at-a-time as int4/float4 (one warp-uniform 16B
// broadcast load each instead of 8 scalar loads) -> L1 wavefronts per edge
// drop from ~4 to ~2.5. Peel to 16B alignment first. 4 independent row
// gathers in flight per warp.
// acc = dis[dst] * sum_e dis[src_e] * x[src_e]
// Fused epilogue: xout = acc (unless LAST); out (+)= w[widx]*acc [+ w0*emb if FIRST].
template<bool FIRST, bool LAST>
__global__ void k_gather(const float* __restrict__ xin,
                         float* __restrict__ xout,
                         const float* __restrict__ emb,
                         int widx) {
    int t = threadIdx.x;
    int node = blockIdx.x * 8 + (t >> 5);
    int lane = t & 31;
    if (node >= N_NODES) return;
    int i0 = rowptr_at(node);
    int i1 = rowptr_at(node + 1);
    float ax = 0.f, ay = 0.f;
    int i = i0;
    // peel until i is 4-aligned (warp-uniform)
    while ((i & 3) && i < i1) {
        int   s = __ldg(&g_csrc[i]);
        float w = __ldg(&g_cw[i]);
        float2 v = *reinterpret_cast<const float2*>(xin + (size_t)s * DIM + lane * 2);
        ax = fmaf(w, v.x, ax);
        ay = fmaf(w, v.y, ay);
        i++;
    }
    // main loop: one int4 + one float4 broadcast load per 4 edges
    for (; i + 4 <= i1; i += 4) {
        int4   s4 = *reinterpret_cast<const int4*>(g_csrc + i);
        float4 w4 = *reinterpret_cast<const float4*>(g_cw + i);
        float2 v0 = *reinterpret_cast<const float2*>(xin + (size_t)s4.x * DIM + lane * 2);
        float2 v1 = *reinterpret_cast<const float2*>(xin + (size_t)s4.y * DIM + lane * 2);
        float2 v2 = *reinterpret_cast<const float2*>(xin + (size_t)s4.z * DIM + lane * 2);
        float2 v3 = *reinterpret_cast<const float2*>(xin + (size_t)s4.w * DIM + lane * 2);
        ax = fmaf(w4.x, v0.x, ax); ay = fmaf(w4.x, v0.y, ay);
        ax = fmaf(w4.y, v1.x, ax); ay = fmaf(w4.y, v1.y, ay);
        ax = fmaf(w4.z, v2.x, ax); ay = fmaf(w4.z, v2.y, ay);
        ax = fmaf(w4.w, v3.x, ax); ay = fmaf(w4.w, v3.y, ay);
    }
    // remainder
    for (; i < i1; i++) {
        int   s = __ldg(&g_csrc[i]);
        float w = __ldg(&g_cw[i]);
        float2 v = *reinterpret_cast<const float2*>(xin + (size_t)s * DIM + lane * 2);
        ax = fmaf(w, v.x, ax);
        ay = fmaf(w, v.y, ay);
    }
    float disd = g_dis[node];
    ax *= disd; ay *= disd;
    size_t o = (size_t)node * DIM + lane * 2;
    if (!LAST)
        *reinterpret_cast<float2*>(xout + o) = make_float2(ax, ay);
    float wl = g_w[widx];
    float2* po = reinterpret_cast<float2*>(g_out + o);
    if (FIRST) {
        float2 e2 = *reinterpret_cast<const float2*>(emb + o);
        float w0 = g_w[0];
        *po = make_float2(fmaf(w0, e2.x, wl * ax), fmaf(w0, e2.y, wl * ay));
    } else {
        float2 c = *po;
        *po = make_float2(fmaf(wl, ax, c.x), fmaf(wl, ay, c.y));
    }
}

// dot: 16 lanes per edge, float4 per lane (256B coalesced row reads)
__global__ void k_dot(const int* __restrict__ eli, float* __restrict__ res) {
    int gt = blockIdx.x * blockDim.x + threadIdx.x;
    int e = gt >> 4, l = gt & 15;
    if (e >= E_EDGES) return;
    int a = __ldg(&eli[e]);
    int b = __ldg(&eli[E_EDGES + e]);
    float4 va = *reinterpret_cast<const float4*>(g_out + (size_t)a * DIM + l * 4);
    float4 vb = *reinterpret_cast<const float4*>(g_out + (size_t)b * DIM + l * 4);
    float s = va.x * vb.x + va.y * vb.y + va.z * vb.z + va.w * vb.w;
    #pragma unroll
    for (int off = 8; off > 0; off >>= 1)
        s += __shfl_xor_sync(0xffffffffu, s, off);
    if (l == 0) res[e] = s;
}

extern "C" void kernel_launch(void* const* d_in, const int* in_sizes, int n_in,
                              void* d_out, int out_size) {
    const int*   edge_index = (const int*)d_in[0];
    const int*   edge_label = (const int*)d_in[1];
    const float* emb        = (const float*)d_in[2];
    const float* alpha      = (const float*)d_in[3];
    float*       res        = (float*)d_out;

    float *x1, *x2;
    int   *cntp;
    cudaGetSymbolAddress((void**)&x1,   g_x1);
    cudaGetSymbolAddress((void**)&x2,   g_x2);
    cudaGetSymbolAddress((void**)&cntp, g_cnt);

    const int TB = 256;
    const int nblkE = (E_EDGES + TB - 1) / TB;
    const int nblkG = (N_NODES + 7) / 8;          // 8 nodes per 256-thread block

    // CSR build (histogram zeroed by async memset)
    cudaMemsetAsync(cntp, 0, N_NODES * sizeof(int));
    k_count<<<nblkE, TB>>>(edge_index);
    k_scan1<<<SCAN_NBLK, SCAN_B>>>();
    k_scan2<<<1, 512>>>(alpha);
    k_fill<<<nblkE, TB>>>(edge_index);

    // propagation (gather, no fp atomics), out-accum fused
    k_gather<true,  false><<<nblkG, TB>>>(emb, x1, emb, 1);
    k_gather<false, false><<<nblkG, TB>>>(x1, x2, nullptr, 2);
    k_gather<false, true ><<<nblkG, TB>>>(x2, x1, nullptr, 3);

    // per-edge dot over edge_label_index
    long long dot_threads = (long long)E_EDGES * 16;
    k_dot<<<(int)((dot_threads + TB - 1) / TB), TB>>>(edge_label, res);
}

// round 14
// speedup vs baseline: 1.1611x; 1.1611x over previous
#include <cuda_runtime.h>
#include <cuda_bf16.h>

#define N_NODES 100000
#define E_EDGES 1250000
#define DIM     64
#define NL      3
#define SCAN_B  256
#define SCAN_NBLK ((N_NODES + SCAN_B - 1) / SCAN_B)   // 391

// ---- scratch (no allocations allowed) ----
__device__ float g_w[NL + 1];
__device__ int   g_cnt[N_NODES];
__device__ int   g_rank[E_EDGES];
__device__ int   g_excl[N_NODES];
__device__ int   g_bsum[512];
__device__ int   g_boff[512];
__device__ int   g_csrc[E_EDGES];
__device__ float g_cw[E_EDGES];
__device__ float g_dis[N_NODES];
__device__ float g_x1[N_NODES * DIM];
__device__ float g_x2[N_NODES * DIM];
__device__ float g_out[N_NODES * DIM];

// histogram; atomic return value = unique within-row rank
__global__ void k_count(const int* __restrict__ edge_index) {
    int e = blockIdx.x * blockDim.x + threadIdx.x;
    if (e < E_EDGES)
        g_rank[e] = atomicAdd(&g_cnt[edge_index[E_EDGES + e]], 1);
}

// per-block scan + block sums; also dis = rsqrt(deg) (fused)
__global__ void k_scan1() {
    __shared__ int sh[SCAN_B];
    int t = threadIdx.x, b = blockIdx.x, i = b * SCAN_B + t;
    int v = (i < N_NODES) ? g_cnt[i] : 0;
    if (i < N_NODES)
        g_dis[i] = (v > 0) ? rsqrtf((float)v) : 0.f;
    sh[t] = v; __syncthreads();
    #pragma unroll
    for (int off = 1; off < SCAN_B; off <<= 1) {
        int u = (t >= off) ? sh[t - off] : 0;
        __syncthreads();
        sh[t] += u;
        __syncthreads();
    }
    if (i < N_NODES) g_excl[i] = sh[t] - v;
    if (t == SCAN_B - 1) g_bsum[b] = sh[t];
}

// scan the 391 block sums in a single 512-thread block; thread 0 also does softmax
__global__ void k_scan2(const float* __restrict__ alpha) {
    __shared__ int sh[512];
    int t = threadIdx.x;
    if (t == 0) {
        float m = alpha[0];
        for (int j = 1; j <= NL; j++) m = fmaxf(m, alpha[j]);
        float s = 0.f, e[NL + 1];
        for (int j = 0; j <= NL; j++) { e[j] = __expf(alpha[j] - m); s += e[j]; }
        for (int j = 0; j <= NL; j++) g_w[j] = e[j] / s;
    }
    int v = (t < SCAN_NBLK) ? g_bsum[t] : 0;
    sh[t] = v; __syncthreads();
    #pragma unroll
    for (int off = 1; off < 512; off <<= 1) {
        int u = (t >= off) ? sh[t - off] : 0;
        __syncthreads();
        sh[t] += u;
        __syncthreads();
    }
    if (t < SCAN_NBLK) g_boff[t] = sh[t] - v;
}

// rowptr(i) computed on the fly by consumers: g_excl[i] + g_boff[i >> 8]
__device__ __forceinline__ int rowptr_at(int i) {
    return (i < N_NODES) ? (g_excl[i] + g_boff[i >> 8]) : E_EDGES;
}

// fill CSR: no atomics (rank precomputed); payload = src index + dis[src].
// dis[dst] factor applied in gather epilogue (row-uniform).
__global__ void k_fill(const int* __restrict__ edge_index) {
    int e = blockIdx.x * blockDim.x + threadIdx.x;
    if (e < E_EDGES) {
        int s = edge_index[e];
        int t = edge_index[E_EDGES + e];
        int pos = g_excl[t] + __ldg(&g_boff[t >> 8]) + g_rank[e];
        g_csrc[pos] = s;
        g_cw[pos]   = g_dis[s];
    }
}

// Gather propagation: one warp per dst node, float2 per lane (256B row).
// 4-way unroll -> 4 independent row gathers in flight per warp.
// acc = dis[dst] * sum_e dis[src_e] * x[src_e]
// Fused epilogue: xout = acc (unless LAST); out (+)= w[widx]*acc [+ w0*emb if FIRST].
template<bool FIRST, bool LAST>
__global__ void k_gather(const float* __restrict__ xin,
                         float* __restrict__ xout,
                         const float* __restrict__ emb,
                         int widx) {
    int t = threadIdx.x;
    int node = blockIdx.x * 8 + (t >> 5);
    int lane = t & 31;
    if (node >= N_NODES) return;
    int i0 = rowptr_at(node);
    int i1 = rowptr_at(node + 1);
    float ax = 0.f, ay = 0.f;
    int i = i0;
    int lim = i1 - 3;
    for (; i < lim; i += 4) {
        int   s0 = __ldg(&g_csrc[i]);
        int   s1 = __ldg(&g_csrc[i + 1]);
        int   s2 = __ldg(&g_csrc[i + 2]);
        int   s3 = __ldg(&g_csrc[i + 3]);
        float w0 = __ldg(&g_cw[i]);
        float w1 = __ldg(&g_cw[i + 1]);
        float w2 = __ldg(&g_cw[i + 2]);
        float w3 = __ldg(&g_cw[i + 3]);
        float2 v0 = *reinterpret_cast<const float2*>(xin + (size_t)s0 * DIM + lane * 2);
        float2 v1 = *reinterpret_cast<const float2*>(xin + (size_t)s1 * DIM + lane * 2);
        float2 v2 = *reinterpret_cast<const float2*>(xin + (size_t)s2 * DIM + lane * 2);
        float2 v3 = *reinterpret_cast<const float2*>(xin + (size_t)s3 * DIM + lane * 2);
        ax = fmaf(w0, v0.x, ax); ay = fmaf(w0, v0.y, ay);
        ax = fmaf(w1, v1.x, ax); ay = fmaf(w1, v1.y, ay);
        ax = fmaf(w2, v2.x, ax); ay = fmaf(w2, v2.y, ay);
        ax = fmaf(w3, v3.x, ax); ay = fmaf(w3, v3.y, ay);
    }
    for (; i < i1; i++) {
        int   s = __ldg(&g_csrc[i]);
        float w = __ldg(&g_cw[i]);
        float2 v = *reinterpret_cast<const float2*>(xin + (size_t)s * DIM + lane * 2);
        ax = fmaf(w, v.x, ax);
        ay = fmaf(w, v.y, ay);
    }
    float disd = g_dis[node];
    ax *= disd; ay *= disd;
    size_t o = (size_t)node * DIM + lane * 2;
    if (!LAST)
        *reinterpret_cast<float2*>(xout + o) = make_float2(ax, ay);
    float wl = g_w[widx];
    float2* po = reinterpret_cast<float2*>(g_out + o);
    if (FIRST) {
        float2 e2 = *reinterpret_cast<const float2*>(emb + o);
        float w0 = g_w[0];
        *po = make_float2(fmaf(w0, e2.x, wl * ax), fmaf(w0, e2.y, wl * ay));
    } else {
        float2 c = *po;
        *po = make_float2(fmaf(wl, ax, c.x), fmaf(wl, ay, c.y));
    }
}

// dot: 16 lanes per edge, float4 per lane (256B coalesced row reads)
__global__ void k_dot(const int* __restrict__ eli, float* __restrict__ res) {
    int gt = blockIdx.x * blockDim.x + threadIdx.x;
    int e = gt >> 4, l = gt & 15;
    if (e >= E_EDGES) return;
    int a = __ldg(&eli[e]);
    int b = __ldg(&eli[E_EDGES + e]);
    float4 va = *reinterpret_cast<const float4*>(g_out + (size_t)a * DIM + l * 4);
    float4 vb = *reinterpret_cast<const float4*>(g_out + (size_t)b * DIM + l * 4);
    float s = va.x * vb.x + va.y * vb.y + va.z * vb.z + va.w * vb.w;
    #pragma unroll
    for (int off = 8; off > 0; off >>= 1)
        s += __shfl_xor_sync(0xffffffffu, s, off);
    if (l == 0) res[e] = s;
}

extern "C" void kernel_launch(void* const* d_in, const int* in_sizes, int n_in,
                              void* d_out, int out_size) {
    const int*   edge_index = (const int*)d_in[0];
    const int*   edge_label = (const int*)d_in[1];
    const float* emb        = (const float*)d_in[2];
    const float* alpha      = (const float*)d_in[3];
    float*       res        = (float*)d_out;

    float *x1, *x2;
    int   *cntp;
    cudaGetSymbolAddress((void**)&x1,   g_x1);
    cudaGetSymbolAddress((void**)&x2,   g_x2);
    cudaGetSymbolAddress((void**)&cntp, g_cnt);

    const int TB = 256;
    const int nblkE = (E_EDGES + TB - 1) / TB;
    const int nblkG = (N_NODES + 7) / 8;          // 8 nodes per 256-thread block

    // CSR build (histogram zeroed by async memset)
    cudaMemsetAsync(cntp, 0, N_NODES * sizeof(int));
    k_count<<<nblkE, TB>>>(edge_index);
    k_scan1<<<SCAN_NBLK, SCAN_B>>>();
    k_scan2<<<1, 512>>>(alpha);
    k_fill<<<nblkE, TB>>>(edge_index);

    // propagation (gather, no fp atomics), out-accum fused
    k_gather<true,  false><<<nblkG, TB>>>(emb, x1, emb, 1);
    k_gather<false, false><<<nblkG, TB>>>(x1, x2, nullptr, 2);
    k_gather<false, true ><<<nblkG, TB>>>(x2, x1, nullptr, 3);

    // per-edge dot over edge_label_index
    long long dot_threads = (long long)E_EDGES * 16;
    k_dot<<<(int)((dot_threads + TB - 1) / TB), TB>>>(edge_label, res);
}

// round 15
// speedup vs baseline: 1.1743x; 1.0113x over previous
#include <cuda_runtime.h>
#include <cuda_bf16.h>

#define N_NODES 100000
#define E_EDGES 1250000
#define DIM     64
#define NL      3
#define SCAN_B  256
#define SCAN_NBLK ((N_NODES + SCAN_B - 1) / SCAN_B)   // 391

// ---- scratch (no allocations allowed) ----
__device__ float g_w[NL + 1];
__device__ int   g_cnt[N_NODES];
__device__ int   g_rank[E_EDGES];
__device__ int   g_excl[N_NODES];
__device__ int   g_bsum[512];
__device__ int   g_boff[512];
__device__ int   g_csrc[E_EDGES];
__device__ float g_dis[N_NODES];
__device__ float g_y0[N_NODES * DIM];
__device__ float g_x1[N_NODES * DIM];
__device__ float g_x2[N_NODES * DIM];
__device__ float g_out[N_NODES * DIM];

// histogram; atomic return value = unique within-row rank
__global__ void k_count(const int* __restrict__ edge_index) {
    int e = blockIdx.x * blockDim.x + threadIdx.x;
    if (e < E_EDGES)
        g_rank[e] = atomicAdd(&g_cnt[edge_index[E_EDGES + e]], 1);
}

// per-block scan + block sums; also dis = rsqrt(deg) (fused)
__global__ void k_scan1() {
    __shared__ int sh[SCAN_B];
    int t = threadIdx.x, b = blockIdx.x, i = b * SCAN_B + t;
    int v = (i < N_NODES) ? g_cnt[i] : 0;
    if (i < N_NODES)
        g_dis[i] = (v > 0) ? rsqrtf((float)v) : 0.f;
    sh[t] = v; __syncthreads();
    #pragma unroll
    for (int off = 1; off < SCAN_B; off <<= 1) {
        int u = (t >= off) ? sh[t - off] : 0;
        __syncthreads();
        sh[t] += u;
        __syncthreads();
    }
    if (i < N_NODES) g_excl[i] = sh[t] - v;
    if (t == SCAN_B - 1) g_bsum[b] = sh[t];
}

// scan the 391 block sums in a single 512-thread block; thread 0 also does softmax
__global__ void k_scan2(const float* __restrict__ alpha) {
    __shared__ int sh[512];
    int t = threadIdx.x;
    if (t == 0) {
        float m = alpha[0];
        for (int j = 1; j <= NL; j++) m = fmaxf(m, alpha[j]);
        float s = 0.f, e[NL + 1];
        for (int j = 0; j <= NL; j++) { e[j] = __expf(alpha[j] - m); s += e[j]; }
        for (int j = 0; j <= NL; j++) g_w[j] = e[j] / s;
    }
    int v = (t < SCAN_NBLK) ? g_bsum[t] : 0;
    sh[t] = v; __syncthreads();
    #pragma unroll
    for (int off = 1; off < 512; off <<= 1) {
        int u = (t >= off) ? sh[t - off] : 0;
        __syncthreads();
        sh[t] += u;
        __syncthreads();
    }
    if (t < SCAN_NBLK) g_boff[t] = sh[t] - v;
}

// rowptr(i) computed on the fly by consumers: g_excl[i] + g_boff[i >> 8]
__device__ __forceinline__ int rowptr_at(int i) {
    return (i < N_NODES) ? (g_excl[i] + g_boff[i >> 8]) : E_EDGES;
}

// fill CSR: no atomics (rank precomputed); payload = src index only.
// All normalization is applied via row-uniform scales in the gather epilogue.
__global__ void k_fill(const int* __restrict__ edge_index) {
    int e = blockIdx.x * blockDim.x + threadIdx.x;
    if (e < E_EDGES) {
        int s = edge_index[e];
        int t = edge_index[E_EDGES + e];
        int pos = g_excl[t] + __ldg(&g_boff[t >> 8]) + g_rank[e];
        g_csrc[pos] = s;
    }
}

// y0 = dis ⊙ emb (row-scaled embedding), float4 streaming
__global__ void k_y0(const float* __restrict__ emb) {
    int idx = blockIdx.x * blockDim.x + threadIdx.x;    // one float4 per thread
    if (idx < N_NODES * DIM / 4) {
        int node = idx >> 4;                            // 16 float4 per row
        float d = g_dis[node];
        float4 v = *reinterpret_cast<const float4*>(emb + (size_t)idx * 4);
        *reinterpret_cast<float4*>(g_y0 + (size_t)idx * 4) =
            make_float4(d * v.x, d * v.y, d * v.z, d * v.w);
    }
}

// Gather propagation on y-space: one warp per dst node, float2 per lane.
// acc = sum_e y[src_e]  (pure unweighted row sum; no per-edge weight loads)
// x = dis[dst]*acc;  out (+)= w[widx]*x [+ w0*emb if FIRST];
// y_next = dis[dst]*x (stored unless LAST).
// 4-way unroll -> 4 independent row gathers in flight per warp.
template<bool FIRST, bool LAST>
__global__ void k_gather(const float* __restrict__ yin,
                         float* __restrict__ yout,
                         const float* __restrict__ emb,
                         int widx) {
    int t = threadIdx.x;
    int node = blockIdx.x * 8 + (t >> 5);
    int lane = t & 31;
    if (node >= N_NODES) return;
    int i0 = rowptr_at(node);
    int i1 = rowptr_at(node + 1);
    float ax = 0.f, ay = 0.f;
    int i = i0;
    int lim = i1 - 3;
    for (; i < lim; i += 4) {
        int s0 = __ldg(&g_csrc[i]);
        int s1 = __ldg(&g_csrc[i + 1]);
        int s2 = __ldg(&g_csrc[i + 2]);
        int s3 = __ldg(&g_csrc[i + 3]);
        float2 v0 = *reinterpret_cast<const float2*>(yin + (size_t)s0 * DIM + lane * 2);
        float2 v1 = *reinterpret_cast<const float2*>(yin + (size_t)s1 * DIM + lane * 2);
        float2 v2 = *reinterpret_cast<const float2*>(yin + (size_t)s2 * DIM + lane * 2);
        float2 v3 = *reinterpret_cast<const float2*>(yin + (size_t)s3 * DIM + lane * 2);
        ax += v0.x + v1.x; ay += v0.y + v1.y;
        ax += v2.x + v3.x; ay += v2.y + v3.y;
    }
    for (; i < i1; i++) {
        int s = __ldg(&g_csrc[i]);
        float2 v = *reinterpret_cast<const float2*>(yin + (size_t)s * DIM + lane * 2);
        ax += v.x;
        ay += v.y;
    }
    float disd = g_dis[node];
    float xx = disd * ax, xy = disd * ay;       // x_{l+1} row values
    size_t o = (size_t)node * DIM + lane * 2;
    if (!LAST)
        *reinterpret_cast<float2*>(yout + o) = make_float2(disd * xx, disd * xy);
    float wl = g_w[widx];
    float2* po = reinterpret_cast<float2*>(g_out + o);
    if (FIRST) {
        float2 e2 = *reinterpret_cast<const float2*>(emb + o);
        float w0 = g_w[0];
        *po = make_float2(fmaf(w0, e2.x, wl * xx), fmaf(w0, e2.y, wl * xy));
    } else {
        float2 c = *po;
        *po = make_float2(fmaf(wl, xx, c.x), fmaf(wl, xy, c.y));
    }
}

// dot: 16 lanes per edge, float4 per lane (256B coalesced row reads)
__global__ void k_dot(const int* __restrict__ eli, float* __restrict__ res) {
    int gt = blockIdx.x * blockDim.x + threadIdx.x;
    int e = gt >> 4, l = gt & 15;
    if (e >= E_EDGES) return;
    int a = __ldg(&eli[e]);
    int b = __ldg(&eli[E_EDGES + e]);
    float4 va = *reinterpret_cast<const float4*>(g_out + (size_t)a * DIM + l * 4);
    float4 vb = *reinterpret_cast<const float4*>(g_out + (size_t)b * DIM + l * 4);
    float s = va.x * vb.x + va.y * vb.y + va.z * vb.z + va.w * vb.w;
    #pragma unroll
    for (int off = 8; off > 0; off >>= 1)
        s += __shfl_xor_sync(0xffffffffu, s, off);
    if (l == 0) res[e] = s;
}

extern "C" void kernel_launch(void* const* d_in, const int* in_sizes, int n_in,
                              void* d_out, int out_size) {
    const int*   edge_index = (const int*)d_in[0];
    const int*   edge_label = (const int*)d_in[1];
    const float* emb        = (const float*)d_in[2];
    const float* alpha      = (const float*)d_in[3];
    float*       res        = (float*)d_out;

    float *x1, *x2, *y0;
    int   *cntp;
    cudaGetSymbolAddress((void**)&x1,   g_x1);
    cudaGetSymbolAddress((void**)&x2,   g_x2);
    cudaGetSymbolAddress((void**)&y0,   g_y0);
    cudaGetSymbolAddress((void**)&cntp, g_cnt);

    const int TB = 256;
    const int nblkE = (E_EDGES + TB - 1) / TB;
    const int nblkG = (N_NODES + 7) / 8;          // 8 nodes per 256-thread block
    const int nblkY = (N_NODES * DIM / 4 + TB - 1) / TB;

    // CSR build (histogram zeroed by async memset)
    cudaMemsetAsync(cntp, 0, N_NODES * sizeof(int));
    k_count<<<nblkE, TB>>>(edge_index);
    k_scan1<<<SCAN_NBLK, SCAN_B>>>();
    k_scan2<<<1, 512>>>(alpha);
    k_fill<<<nblkE, TB>>>(edge_index);

    // y0 = dis ⊙ emb, then weightless gather propagation
    k_y0<<<nblkY, TB>>>(emb);
    k_gather<true,  false><<<nblkG, TB>>>(y0, x1, emb, 1);
    k_gather<false, false><<<nblkG, TB>>>(x1, x2, nullptr, 2);
    k_gather<false, true ><<<nblkG, TB>>>(x2, x1, nullptr, 3);

    // per-edge dot over edge_label_index
    long long dot_threads = (long long)E_EDGES * 16;
    k_dot<<<(int)((dot_threads + TB - 1) / TB), TB>>>(edge_label, res);
}

// round 16
// speedup vs baseline: 1.3910x; 1.1846x over previous
#include <cuda_runtime.h>
#include <cuda_bf16.h>
#include <cuda_fp16.h>

#define N_NODES 100000
#define E_EDGES 1250000
#define DIM     64
#define NL      3
#define SCAN_B  256
#define SCAN_NBLK ((N_NODES + SCAN_B - 1) / SCAN_B)   // 391

// ---- scratch (no allocations allowed) ----
__device__ float g_w[NL + 1];
__device__ int   g_cnt[N_NODES];
__device__ int   g_rank[E_EDGES];
__device__ int   g_excl[N_NODES];
__device__ int   g_bsum[512];
__device__ int   g_boff[512];
__device__ int   g_csrc[E_EDGES];
__device__ float g_dis[N_NODES];
__device__ float g_y0[N_NODES * DIM];
__device__ float g_x1[N_NODES * DIM];
__device__ float g_x2[N_NODES * DIM];
__device__ float g_out[N_NODES * DIM];
__device__ __half g_outh[N_NODES * DIM];   // final out, fp16 (dot input)

// histogram; atomic return value = unique within-row rank
__global__ void k_count(const int* __restrict__ edge_index) {
    int e = blockIdx.x * blockDim.x + threadIdx.x;
    if (e < E_EDGES)
        g_rank[e] = atomicAdd(&g_cnt[edge_index[E_EDGES + e]], 1);
}

// per-block scan + block sums; also dis = rsqrt(deg) (fused)
__global__ void k_scan1() {
    __shared__ int sh[SCAN_B];
    int t = threadIdx.x, b = blockIdx.x, i = b * SCAN_B + t;
    int v = (i < N_NODES) ? g_cnt[i] : 0;
    if (i < N_NODES)
        g_dis[i] = (v > 0) ? rsqrtf((float)v) : 0.f;
    sh[t] = v; __syncthreads();
    #pragma unroll
    for (int off = 1; off < SCAN_B; off <<= 1) {
        int u = (t >= off) ? sh[t - off] : 0;
        __syncthreads();
        sh[t] += u;
        __syncthreads();
    }
    if (i < N_NODES) g_excl[i] = sh[t] - v;
    if (t == SCAN_B - 1) g_bsum[b] = sh[t];
}

// scan the 391 block sums in a single 512-thread block; thread 0 also does softmax
__global__ void k_scan2(const float* __restrict__ alpha) {
    __shared__ int sh[512];
    int t = threadIdx.x;
    if (t == 0) {
        float m = alpha[0];
        for (int j = 1; j <= NL; j++) m = fmaxf(m, alpha[j]);
        float s = 0.f, e[NL + 1];
        for (int j = 0; j <= NL; j++) { e[j] = __expf(alpha[j] - m); s += e[j]; }
        for (int j = 0; j <= NL; j++) g_w[j] = e[j] / s;
    }
    int v = (t < SCAN_NBLK) ? g_bsum[t] : 0;
    sh[t] = v; __syncthreads();
    #pragma unroll
    for (int off = 1; off < 512; off <<= 1) {
        int u = (t >= off) ? sh[t - off] : 0;
        __syncthreads();
        sh[t] += u;
        __syncthreads();
    }
    if (t < SCAN_NBLK) g_boff[t] = sh[t] - v;
}

// rowptr(i) computed on the fly by consumers: g_excl[i] + g_boff[i >> 8]
__device__ __forceinline__ int rowptr_at(int i) {
    return (i < N_NODES) ? (g_excl[i] + g_boff[i >> 8]) : E_EDGES;
}

// fill CSR: no atomics (rank precomputed); payload = src index only.
__global__ void k_fill(const int* __restrict__ edge_index) {
    int e = blockIdx.x * blockDim.x + threadIdx.x;
    if (e < E_EDGES) {
        int s = edge_index[e];
        int t = edge_index[E_EDGES + e];
        int pos = g_excl[t] + __ldg(&g_boff[t >> 8]) + g_rank[e];
        g_csrc[pos] = s;
    }
}

// y0 = dis ⊙ emb (row-scaled embedding), float4 streaming
__global__ void k_y0(const float* __restrict__ emb) {
    int idx = blockIdx.x * blockDim.x + threadIdx.x;    // one float4 per thread
    if (idx < N_NODES * DIM / 4) {
        int node = idx >> 4;                            // 16 float4 per row
        float d = g_dis[node];
        float4 v = *reinterpret_cast<const float4*>(emb + (size_t)idx * 4);
        *reinterpret_cast<float4*>(g_y0 + (size_t)idx * 4) =
            make_float4(d * v.x, d * v.y, d * v.z, d * v.w);
    }
}

// Gather propagation on y-space: one warp per dst node, float2 per lane.
// acc = sum_e y[src_e]; x = dis[dst]*acc; out (+)= w[widx]*x [+ w0*emb if FIRST];
// y_next = dis[dst]*x (stored unless LAST). LAST converts final out to fp16.
// All accumulation is fp32; fp16 quantization happens exactly once (LAST).
template<bool FIRST, bool LAST>
__global__ void k_gather(const float* __restrict__ yin,
                         float* __restrict__ yout,
                         const float* __restrict__ emb,
                         int widx) {
    int t = threadIdx.x;
    int node = blockIdx.x * 8 + (t >> 5);
    int lane = t & 31;
    if (node >= N_NODES) return;
    int i0 = rowptr_at(node);
    int i1 = rowptr_at(node + 1);
    float ax = 0.f, ay = 0.f;
    int i = i0;
    int lim = i1 - 3;
    for (; i < lim; i += 4) {
        int s0 = __ldg(&g_csrc[i]);
        int s1 = __ldg(&g_csrc[i + 1]);
        int s2 = __ldg(&g_csrc[i + 2]);
        int s3 = __ldg(&g_csrc[i + 3]);
        float2 v0 = *reinterpret_cast<const float2*>(yin + (size_t)s0 * DIM + lane * 2);
        float2 v1 = *reinterpret_cast<const float2*>(yin + (size_t)s1 * DIM + lane * 2);
        float2 v2 = *reinterpret_cast<const float2*>(yin + (size_t)s2 * DIM + lane * 2);
        float2 v3 = *reinterpret_cast<const float2*>(yin + (size_t)s3 * DIM + lane * 2);
        ax += v0.x + v1.x; ay += v0.y + v1.y;
        ax += v2.x + v3.x; ay += v2.y + v3.y;
    }
    for (; i < i1; i++) {
        int s = __ldg(&g_csrc[i]);
        float2 v = *reinterpret_cast<const float2*>(yin + (size_t)s * DIM + lane * 2);
        ax += v.x;
        ay += v.y;
    }
    float disd = g_dis[node];
    float xx = disd * ax, xy = disd * ay;       // x_{l+1} row values
    size_t o = (size_t)node * DIM + lane * 2;
    if (!LAST)
        *reinterpret_cast<float2*>(yout + o) = make_float2(disd * xx, disd * xy);
    float wl = g_w[widx];
    if (FIRST) {
        float2 e2 = *reinterpret_cast<const float2*>(emb + o);
        float w0 = g_w[0];
        *reinterpret_cast<float2*>(g_out + o) =
            make_float2(fmaf(w0, e2.x, wl * xx), fmaf(w0, e2.y, wl * xy));
    } else if (!LAST) {
        float2 c = *reinterpret_cast<float2*>(g_out + o);
        *reinterpret_cast<float2*>(g_out + o) =
            make_float2(fmaf(wl, xx, c.x), fmaf(wl, xy, c.y));
    } else {
        // final layer: accumulate in fp32, quantize once to fp16
        float2 c = *reinterpret_cast<float2*>(g_out + o);
        float fx = fmaf(wl, xx, c.x), fy = fmaf(wl, xy, c.y);
        *reinterpret_cast<__half2*>(g_outh + o) = __floats2half2_rn(fx, fy);
    }
}

// dot: 8 lanes per edge, 16B (8 halves) per lane -> 128B per row read.
// Accumulation in fp32.
__global__ void k_dot(const int* __restrict__ eli, float* __restrict__ res) {
    int gt = blockIdx.x * blockDim.x + threadIdx.x;
    int e = gt >> 3, l = gt & 7;
    if (e >= E_EDGES) return;
    int a = __ldg(&eli[e]);
    int b = __ldg(&eli[E_EDGES + e]);
    const uint4* pa = reinterpret_cast<const uint4*>(g_outh + (size_t)a * DIM + l * 8);
    const uint4* pb = reinterpret_cast<const uint4*>(g_outh + (size_t)b * DIM + l * 8);
    uint4 ua = *pa;
    uint4 ub = *pb;
    const __half2* ha = reinterpret_cast<const __half2*>(&ua);
    const __half2* hb = reinterpret_cast<const __half2*>(&ub);
    float s = 0.f;
    #pragma unroll
    for (int k = 0; k < 4; k++) {
        float2 fa = __half22float2(ha[k]);
        float2 fb = __half22float2(hb[k]);
        s = fmaf(fa.x, fb.x, s);
        s = fmaf(fa.y, fb.y, s);
    }
    #pragma unroll
    for (int off = 4; off > 0; off >>= 1)
        s += __shfl_xor_sync(0xffffffffu, s, off);
    if (l == 0) res[e] = s;
}

extern "C" void kernel_launch(void* const* d_in, const int* in_sizes, int n_in,
                              void* d_out, int out_size) {
    const int*   edge_index = (const int*)d_in[0];
    const int*   edge_label = (const int*)d_in[1];
    const float* emb        = (const float*)d_in[2];
    const float* alpha      = (const float*)d_in[3];
    float*       res        = (float*)d_out;

    float *x1, *x2, *y0;
    int   *cntp;
    cudaGetSymbolAddress((void**)&x1,   g_x1);
    cudaGetSymbolAddress((void**)&x2,   g_x2);
    cudaGetSymbolAddress((void**)&y0,   g_y0);
    cudaGetSymbolAddress((void**)&cntp, g_cnt);

    const int TB = 256;
    const int nblkE = (E_EDGES + TB - 1) / TB;
    const int nblkG = (N_NODES + 7) / 8;          // 8 nodes per 256-thread block
    const int nblkY = (N_NODES * DIM / 4 + TB - 1) / TB;

    // CSR build (histogram zeroed by async memset)
    cudaMemsetAsync(cntp, 0, N_NODES * sizeof(int));
    k_count<<<nblkE, TB>>>(edge_index);
    k_scan1<<<SCAN_NBLK, SCAN_B>>>();
    k_scan2<<<1, 512>>>(alpha);
    k_fill<<<nblkE, TB>>>(edge_index);

    // y0 = dis ⊙ emb, then weightless gather propagation
    k_y0<<<nblkY, TB>>>(emb);
    k_gather<true,  false><<<nblkG, TB>>>(y0, x1, emb, 1);
    k_gather<false, false><<<nblkG, TB>>>(x1, x2, nullptr, 2);
    k_gather<false, true ><<<nblkG, TB>>>(x2, x1, nullptr, 3);

    // per-edge dot over edge_label_index (fp16 rows, fp32 accumulate)
    long long dot_threads = (long long)E_EDGES * 8;
    k_dot<<<(int)((dot_threads + TB - 1) / TB), TB>>>(edge_label, res);
}

// round 17
// speedup vs baseline: 1.5735x; 1.1312x over previous
#include <cuda_runtime.h>
#include <cuda_bf16.h>
#include <cuda_fp16.h>

#define N_NODES 100000
#define E_EDGES 1250000
#define DIM     64
#define NL      3
#define SCAN_B  256
#define SCAN_NBLK ((N_NODES + SCAN_B - 1) / SCAN_B)   // 391

// ---- scratch (no allocations allowed) ----
__device__ float  g_w[NL + 1];
__device__ int    g_cnt[N_NODES];
__device__ int    g_rank[E_EDGES];
__device__ int    g_excl[N_NODES];
__device__ int    g_bsum[512];
__device__ int    g_boff[512];
__device__ int    g_csrc[E_EDGES];
__device__ float  g_dis[N_NODES];
__device__ __half g_y0[N_NODES * DIM];     // y = dis ⊙ x, fp16 (gather input)
__device__ __half g_y1[N_NODES * DIM];
__device__ __half g_y2[N_NODES * DIM];
__device__ float  g_out[N_NODES * DIM];    // fp32 accumulation of out
__device__ __half g_outh[N_NODES * DIM];   // final out, fp16 (dot input)

// histogram; atomic return value = unique within-row rank
__global__ void k_count(const int* __restrict__ edge_index) {
    int e = blockIdx.x * blockDim.x + threadIdx.x;
    if (e < E_EDGES)
        g_rank[e] = atomicAdd(&g_cnt[edge_index[E_EDGES + e]], 1);
}

// per-block scan + block sums; also dis = rsqrt(deg) (fused)
__global__ void k_scan1() {
    __shared__ int sh[SCAN_B];
    int t = threadIdx.x, b = blockIdx.x, i = b * SCAN_B + t;
    int v = (i < N_NODES) ? g_cnt[i] : 0;
    if (i < N_NODES)
        g_dis[i] = (v > 0) ? rsqrtf((float)v) : 0.f;
    sh[t] = v; __syncthreads();
    #pragma unroll
    for (int off = 1; off < SCAN_B; off <<= 1) {
        int u = (t >= off) ? sh[t - off] : 0;
        __syncthreads();
        sh[t] += u;
        __syncthreads();
    }
    if (i < N_NODES) g_excl[i] = sh[t] - v;
    if (t == SCAN_B - 1) g_bsum[b] = sh[t];
}

// scan the 391 block sums in a single 512-thread block; thread 0 also does softmax
__global__ void k_scan2(const float* __restrict__ alpha) {
    __shared__ int sh[512];
    int t = threadIdx.x;
    if (t == 0) {
        float m = alpha[0];
        for (int j = 1; j <= NL; j++) m = fmaxf(m, alpha[j]);
        float s = 0.f, e[NL + 1];
        for (int j = 0; j <= NL; j++) { e[j] = __expf(alpha[j] - m); s += e[j]; }
        for (int j = 0; j <= NL; j++) g_w[j] = e[j] / s;
    }
    int v = (t < SCAN_NBLK) ? g_bsum[t] : 0;
    sh[t] = v; __syncthreads();
    #pragma unroll
    for (int off = 1; off < 512; off <<= 1) {
        int u = (t >= off) ? sh[t - off] : 0;
        __syncthreads();
        sh[t] += u;
        __syncthreads();
    }
    if (t < SCAN_NBLK) g_boff[t] = sh[t] - v;
}

// rowptr(i) computed on the fly by consumers: g_excl[i] + g_boff[i >> 8]
__device__ __forceinline__ int rowptr_at(int i) {
    return (i < N_NODES) ? (g_excl[i] + g_boff[i >> 8]) : E_EDGES;
}

// fill CSR: no atomics (rank precomputed); payload = src index only.
__global__ void k_fill(const int* __restrict__ edge_index) {
    int e = blockIdx.x * blockDim.x + threadIdx.x;
    if (e < E_EDGES) {
        int s = edge_index[e];
        int t = edge_index[E_EDGES + e];
        int pos = g_excl[t] + __ldg(&g_boff[t >> 8]) + g_rank[e];
        g_csrc[pos] = s;
    }
}

// y0 = fp16(dis ⊙ emb), streaming: 4 floats in -> half2 x2 out per thread
__global__ void k_y0(const float* __restrict__ emb) {
    int idx = blockIdx.x * blockDim.x + threadIdx.x;    // one float4 per thread
    if (idx < N_NODES * DIM / 4) {
        int node = idx >> 4;                            // 16 float4 per row
        float d = g_dis[node];
        float4 v = *reinterpret_cast<const float4*>(emb + (size_t)idx * 4);
        __half2 h0 = __floats2half2_rn(d * v.x, d * v.y);
        __half2 h1 = __floats2half2_rn(d * v.z, d * v.w);
        *reinterpret_cast<__half2*>(g_y0 + (size_t)idx * 4)     = h0;
        *reinterpret_cast<__half2*>(g_y0 + (size_t)idx * 4 + 2) = h1;
    }
}

// Gather propagation on fp16 y-space: one warp per dst node, half2 per lane
// (128B per row -> 1 L1 wavefront). Accumulation fp32.
// acc = sum_e y[src_e]; x = dis[dst]*acc; out (+)= w[widx]*x [+ w0*emb if FIRST];
// y_next = fp16(dis[dst]*x) stored unless LAST; LAST writes fp16 final out.
template<bool FIRST, bool LAST>
__global__ void k_gather(const __half* __restrict__ yin,
                         __half* __restrict__ yout,
                         const float* __restrict__ emb,
                         int widx) {
    int t = threadIdx.x;
    int node = blockIdx.x * 8 + (t >> 5);
    int lane = t & 31;
    if (node >= N_NODES) return;
    int i0 = rowptr_at(node);
    int i1 = rowptr_at(node + 1);
    float ax = 0.f, ay = 0.f;
    int i = i0;
    int lim = i1 - 3;
    for (; i < lim; i += 4) {
        int s0 = __ldg(&g_csrc[i]);
        int s1 = __ldg(&g_csrc[i + 1]);
        int s2 = __ldg(&g_csrc[i + 2]);
        int s3 = __ldg(&g_csrc[i + 3]);
        __half2 h0 = *reinterpret_cast<const __half2*>(yin + (size_t)s0 * DIM + lane * 2);
        __half2 h1 = *reinterpret_cast<const __half2*>(yin + (size_t)s1 * DIM + lane * 2);
        __half2 h2 = *reinterpret_cast<const __half2*>(yin + (size_t)s2 * DIM + lane * 2);
        __half2 h3 = *reinterpret_cast<const __half2*>(yin + (size_t)s3 * DIM + lane * 2);
        float2 v0 = __half22float2(h0);
        float2 v1 = __half22float2(h1);
        float2 v2 = __half22float2(h2);
        float2 v3 = __half22float2(h3);
        ax += v0.x + v1.x; ay += v0.y + v1.y;
        ax += v2.x + v3.x; ay += v2.y + v3.y;
    }
    for (; i < i1; i++) {
        int s = __ldg(&g_csrc[i]);
        float2 v = __half22float2(
            *reinterpret_cast<const __half2*>(yin + (size_t)s * DIM + lane * 2));
        ax += v.x;
        ay += v.y;
    }
    float disd = g_dis[node];
    float xx = disd * ax, xy = disd * ay;       // x_{l+1} row values (fp32)
    size_t o = (size_t)node * DIM + lane * 2;
    if (!LAST)
        *reinterpret_cast<__half2*>(yout + o) = __floats2half2_rn(disd * xx, disd * xy);
    float wl = g_w[widx];
    if (FIRST) {
        float2 e2 = *reinterpret_cast<const float2*>(emb + o);
        float w0 = g_w[0];
        *reinterpret_cast<float2*>(g_out + o) =
            make_float2(fmaf(w0, e2.x, wl * xx), fmaf(w0, e2.y, wl * xy));
    } else if (!LAST) {
        float2 c = *reinterpret_cast<float2*>(g_out + o);
        *reinterpret_cast<float2*>(g_out + o) =
            make_float2(fmaf(wl, xx, c.x), fmaf(wl, xy, c.y));
    } else {
        // final layer: accumulate in fp32, quantize once to fp16
        float2 c = *reinterpret_cast<float2*>(g_out + o);
        float fx = fmaf(wl, xx, c.x), fy = fmaf(wl, xy, c.y);
        *reinterpret_cast<__half2*>(g_outh + o) = __floats2half2_rn(fx, fy);
    }
}

// dot: 8 lanes per edge, 16B (8 halves) per lane -> 128B per row read.
// Accumulation in fp32.
__global__ void k_dot(const int* __restrict__ eli, float* __restrict__ res) {
    int gt = blockIdx.x * blockDim.x + threadIdx.x;
    int e = gt >> 3, l = gt & 7;
    if (e >= E_EDGES) return;
    int a = __ldg(&eli[e]);
    int b = __ldg(&eli[E_EDGES + e]);
    const uint4* pa = reinterpret_cast<const uint4*>(g_outh + (size_t)a * DIM + l * 8);
    const uint4* pb = reinterpret_cast<const uint4*>(g_outh + (size_t)b * DIM + l * 8);
    uint4 ua = *pa;
    uint4 ub = *pb;
    const __half2* ha = reinterpret_cast<const __half2*>(&ua);
    const __half2* hb = reinterpret_cast<const __half2*>(&ub);
    float s = 0.f;
    #pragma unroll
    for (int k = 0; k < 4; k++) {
        float2 fa = __half22float2(ha[k]);
        float2 fb = __half22float2(hb[k]);
        s = fmaf(fa.x, fb.x, s);
        s = fmaf(fa.y, fb.y, s);
    }
    #pragma unroll
    for (int off = 4; off > 0; off >>= 1)
        s += __shfl_xor_sync(0xffffffffu, s, off);
    if (l == 0) res[e] = s;
}

extern "C" void kernel_launch(void* const* d_in, const int* in_sizes, int n_in,
                              void* d_out, int out_size) {
    const int*   edge_index = (const int*)d_in[0];
    const int*   edge_label = (const int*)d_in[1];
    const float* emb        = (const float*)d_in[2];
    const float* alpha      = (const float*)d_in[3];
    float*       res        = (float*)d_out;

    __half *y0, *y1, *y2;
    int    *cntp;
    cudaGetSymbolAddress((void**)&y0,   g_y0);
    cudaGetSymbolAddress((void**)&y1,   g_y1);
    cudaGetSymbolAddress((void**)&y2,   g_y2);
    cudaGetSymbolAddress((void**)&cntp, g_cnt);

    const int TB = 256;
    const int nblkE = (E_EDGES + TB - 1) / TB;
    const int nblkG = (N_NODES + 7) / 8;          // 8 nodes per 256-thread block
    const int nblkY = (N_NODES * DIM / 4 + TB - 1) / TB;

    // CSR build (histogram zeroed by async memset)
    cudaMemsetAsync(cntp, 0, N_NODES * sizeof(int));
    k_count<<<nblkE, TB>>>(edge_index);
    k_scan1<<<SCAN_NBLK, SCAN_B>>>();
    k_scan2<<<1, 512>>>(alpha);
    k_fill<<<nblkE, TB>>>(edge_index);

    // y0 = fp16(dis ⊙ emb), then weightless fp16 gather propagation
    k_y0<<<nblkY, TB>>>(emb);
    k_gather<true,  false><<<nblkG, TB>>>(y0, y1, emb, 1);
    k_gather<false, false><<<nblkG, TB>>>(y1, y2, nullptr, 2);
    k_gather<false, true ><<<nblkG, TB>>>(y2, y1, nullptr, 3);

    // per-edge dot over edge_label_index (fp16 rows, fp32 accumulate)
    long long dot_threads = (long long)E_EDGES * 8;
    k_dot<<<(int)((dot_threads + TB - 1) / TB), TB>>>(edge_label, res);
}